// round 6
// baseline (speedup 1.0000x reference)
#include <cuda_runtime.h>
#include <cuda_bf16.h>
#include <math.h>
#include <stdint.h>

// Problem constants (fixed by setup_inputs): B=2048, K=128, D=256
#define BB 2048
#define KK 128
#define DD 256

#define BM 32      // b-rows per block
#define BN 16      // k-cols per block
#define RPITCH 520 // row pitch in FLOATS for split tiles (260 float2 slots)
#define NTHREADS 128

__device__ __forceinline__ uint32_t f2tf32(float v) {
    uint32_t r; asm("cvt.rna.tf32.f32 %0, %1;" : "=r"(r) : "f"(v)); return r;
}

__device__ __forceinline__ void mma_tf32(float* d, uint32_t a0, uint32_t a1, uint32_t a2,
                                         uint32_t a3, uint32_t b0, uint32_t b1) {
    asm volatile("mma.sync.aligned.m16n8k8.row.col.f32.tf32.tf32.f32 "
                 "{%0,%1,%2,%3}, {%4,%5,%6,%7}, {%8,%9}, {%0,%1,%2,%3};"
                 : "+f"(d[0]), "+f"(d[1]), "+f"(d[2]), "+f"(d[3])
                 : "r"(a0), "r"(a1), "r"(a2), "r"(a3), "r"(b0), "r"(b1));
}

// logits[b][k] = 2*an_k * asinh( 2*(S*xa + T*ya)*den / (den^2 - (S^2*x2 + 2*S*T*xy + T^2*y2)) )
// g = z_k . y_b, xy = s_k*g, ya = t_k*g, S = 1+2xy+y2, den = 1+2xy+x2*y2, T = 1-x2

__global__ void __launch_bounds__(NTHREADS, 2)
mlr_logits_kernel(const float* __restrict__ Y,   // output_before (B, D)
                  const float* __restrict__ Z,   // z_mlr (K, D)
                  const float* __restrict__ R,   // mlr_r (K, 1)
                  float* __restrict__ Out)       // (B, K)
{
    extern __shared__ float smem[];
    float* ysp   = smem;                     // BM * RPITCH  (float2 hi/lo interleaved)
    float* zsp   = ysp + BM * RPITCH;        // BN * RPITCH
    float* ypart = zsp + BN * RPITCH;        // 128
    float* zpart = ypart + NTHREADS;         // 64
    float* s_s   = zpart + 64;               // BN
    float* s_t   = s_s + BN;                 // BN
    float* s_x2  = s_t + BN;                 // BN
    float* s_xa  = s_x2 + BN;                // BN
    float* s_an2 = s_xa + BN;                // BN
    float* s_y2  = s_an2 + BN;               // BM

    const int tid  = threadIdx.x;
    const int b0   = blockIdx.x * BM;
    const int k0   = blockIdx.y * BN;
    const int warp = tid >> 5;
    const int lane = tid & 31;

    // ---- load + split Y tile (BM x D) -> float2(hi,lo) in smem ----
    #pragma unroll
    for (int idx = tid; idx < BM * (DD / 4); idx += NTHREADS) {
        int row = idx >> 6;
        int c4  = idx & 63;
        float4 v = reinterpret_cast<const float4*>(Y + (size_t)(b0 + row) * DD)[c4];
        uint32_t h0 = f2tf32(v.x), h1 = f2tf32(v.y), h2 = f2tf32(v.z), h3 = f2tf32(v.w);
        float4 p0, p1;
        p0.x = __uint_as_float(h0); p0.y = __uint_as_float(f2tf32(v.x - __uint_as_float(h0)));
        p0.z = __uint_as_float(h1); p0.w = __uint_as_float(f2tf32(v.y - __uint_as_float(h1)));
        p1.x = __uint_as_float(h2); p1.y = __uint_as_float(f2tf32(v.z - __uint_as_float(h2)));
        p1.z = __uint_as_float(h3); p1.w = __uint_as_float(f2tf32(v.w - __uint_as_float(h3)));
        float* dst = ysp + row * RPITCH + c4 * 8;
        *reinterpret_cast<float4*>(dst)     = p0;
        *reinterpret_cast<float4*>(dst + 4) = p1;
    }
    // ---- load + split Z tile (BN x D) ----
    #pragma unroll
    for (int idx = tid; idx < BN * (DD / 4); idx += NTHREADS) {
        int row = idx >> 6;
        int c4  = idx & 63;
        float4 v = reinterpret_cast<const float4*>(Z + (size_t)(k0 + row) * DD)[c4];
        uint32_t h0 = f2tf32(v.x), h1 = f2tf32(v.y), h2 = f2tf32(v.z), h3 = f2tf32(v.w);
        float4 p0, p1;
        p0.x = __uint_as_float(h0); p0.y = __uint_as_float(f2tf32(v.x - __uint_as_float(h0)));
        p0.z = __uint_as_float(h1); p0.w = __uint_as_float(f2tf32(v.y - __uint_as_float(h1)));
        p1.x = __uint_as_float(h2); p1.y = __uint_as_float(f2tf32(v.z - __uint_as_float(h2)));
        p1.z = __uint_as_float(h3); p1.w = __uint_as_float(f2tf32(v.w - __uint_as_float(h3)));
        float* dst = zsp + row * RPITCH + c4 * 8;
        *reinterpret_cast<float4*>(dst)     = p0;
        *reinterpret_cast<float4*>(dst + 4) = p1;
    }
    __syncthreads();

    // ---- cooperative row norms from split data (v = hi + lo) ----
    {
        const int row = tid >> 2;   // 0..31
        const int q   = tid & 3;
        const float* base = ysp + row * RPITCH + q * 128;  // 64 elems = 128 floats
        float a0 = 0.f, a1 = 0.f;
        #pragma unroll
        for (int j = 0; j < 16; j++) {
            float4 p0 = *reinterpret_cast<const float4*>(base + j * 8);
            float4 p1 = *reinterpret_cast<const float4*>(base + j * 8 + 4);
            float v0 = p0.x + p0.y, v1 = p0.z + p0.w;
            float v2 = p1.x + p1.y, v3 = p1.z + p1.w;
            a0 = fmaf(v0, v0, a0); a1 = fmaf(v1, v1, a1);
            a0 = fmaf(v2, v2, a0); a1 = fmaf(v3, v3, a1);
        }
        ypart[tid] = a0 + a1;
    }
    if (tid < 64) {
        const int row = tid >> 2;   // 0..15
        const int q   = tid & 3;
        const float* base = zsp + row * RPITCH + q * 128;
        float a0 = 0.f, a1 = 0.f;
        #pragma unroll
        for (int j = 0; j < 16; j++) {
            float4 p0 = *reinterpret_cast<const float4*>(base + j * 8);
            float4 p1 = *reinterpret_cast<const float4*>(base + j * 8 + 4);
            float v0 = p0.x + p0.y, v1 = p0.z + p0.w;
            float v2 = p1.x + p1.y, v3 = p1.z + p1.w;
            a0 = fmaf(v0, v0, a0); a1 = fmaf(v1, v1, a1);
            a0 = fmaf(v2, v2, a0); a1 = fmaf(v3, v3, a1);
        }
        zpart[tid] = a0 + a1;
    }
    __syncthreads();

    if (tid < BN) {
        int row = tid;
        float zn2 = (zpart[row * 4 + 0] + zpart[row * 4 + 1]) +
                    (zpart[row * 4 + 2] + zpart[row * 4 + 3]);
        float zn  = sqrtf(zn2);
        float r   = R[k0 + row];
        float un  = fmaxf(fabsf(r) * zn, 1e-15f);
        float s   = -tanhf(un) * r / un;
        float th  = tanhf(r);
        float ic2 = 1.0f - th * th;      // 1/cosh(r)^2
        float an  = zn * ic2;
        float t   = ic2 / fmaxf(an, 1e-12f);
        s_s[row]   = s;
        s_t[row]   = t;
        s_x2[row]  = s * s * zn2;
        s_xa[row]  = s * zn2 * t;
        s_an2[row] = 2.0f * an;
    } else if (tid >= 32 && tid < 32 + BM) {
        int row = tid - 32;
        s_y2[row] = (ypart[row * 4 + 0] + ypart[row * 4 + 1]) +
                    (ypart[row * 4 + 2] + ypart[row * 4 + 3]);
    }
    __syncthreads();

    // ---- tensor GEMM: 4 warps, each 16(m) x 8(n), m16n8k8 tf32, 3xTF32 ----
    const int mw = (warp >> 1) * 16;    // 0,16
    const int nw = (warp & 1) * 8;      // 0,8
    const int g  = lane >> 2;
    const int c  = lane & 3;

    const float* aB = ysp + (mw + g) * RPITCH + c * 2;
    const float* bB = zsp + (nw + g) * RPITCH + c * 2;

    float P0[4] = {0,0,0,0}, P1[4] = {0,0,0,0};
    float Qa0[4] = {0,0,0,0}, Qa1[4] = {0,0,0,0};
    float Qb0[4] = {0,0,0,0}, Qb1[4] = {0,0,0,0};

    #pragma unroll 8
    for (int t = 0; t < DD / 8; t++) {
        const int o = t * 16;            // dk*2 floats
        float2 af0 = *reinterpret_cast<const float2*>(aB + o);
        float2 af1 = *reinterpret_cast<const float2*>(aB + 8 * RPITCH + o);
        float2 af2 = *reinterpret_cast<const float2*>(aB + o + 8);
        float2 af3 = *reinterpret_cast<const float2*>(aB + 8 * RPITCH + o + 8);
        float2 bf0 = *reinterpret_cast<const float2*>(bB + o);
        float2 bf1 = *reinterpret_cast<const float2*>(bB + o + 8);

        uint32_t ah0 = __float_as_uint(af0.x), ah1 = __float_as_uint(af1.x);
        uint32_t ah2 = __float_as_uint(af2.x), ah3 = __float_as_uint(af3.x);
        uint32_t al0 = __float_as_uint(af0.y), al1 = __float_as_uint(af1.y);
        uint32_t al2 = __float_as_uint(af2.y), al3 = __float_as_uint(af3.y);
        uint32_t bh0 = __float_as_uint(bf0.x), bh1 = __float_as_uint(bf1.x);
        uint32_t bl0 = __float_as_uint(bf0.y), bl1 = __float_as_uint(bf1.y);

        if (t & 1) {
            mma_tf32(P1,  ah0, ah1, ah2, ah3, bh0, bh1);
            mma_tf32(Qa1, ah0, ah1, ah2, ah3, bl0, bl1);
            mma_tf32(Qb1, al0, al1, al2, al3, bh0, bh1);
        } else {
            mma_tf32(P0,  ah0, ah1, ah2, ah3, bh0, bh1);
            mma_tf32(Qa0, ah0, ah1, ah2, ah3, bl0, bl1);
            mma_tf32(Qb0, al0, al1, al2, al3, bh0, bh1);
        }
    }

    // ---- epilogue: 4 outputs per thread ----
    const int rows[2] = { mw + g, mw + g + 8 };
    const int cols[2] = { nw + 2 * c, nw + 2 * c + 1 };

    #pragma unroll
    for (int i = 0; i < 2; i++) {
        float y2 = s_y2[rows[i]];
        #pragma unroll
        for (int j = 0; j < 2; j++) {
            int sl = i * 2 + j;
            int kl = cols[j];
            float gv = ((P0[sl] + P1[sl]) + (Qa0[sl] + Qa1[sl])) + (Qb0[sl] + Qb1[sl]);
            float s   = s_s[kl];
            float t   = s_t[kl];
            float x2  = s_x2[kl];
            float xa  = s_xa[kl];
            float an2 = s_an2[kl];
            float T   = 1.0f - x2;
            float xy = s * gv;
            float ya = t * gv;
            float S   = fmaf(2.0f, xy, 1.0f) + y2;
            float den = fmaf(2.0f, xy, 1.0f) + x2 * y2;
            float P   = S * S * x2 + 2.0f * S * T * xy + T * T * y2;
            float v   = 2.0f * (S * xa + T * ya) * den / (den * den - P);
            Out[(size_t)(b0 + rows[i]) * KK + (k0 + kl)] = an2 * asinhf(v);
        }
    }
}

extern "C" void kernel_launch(void* const* d_in, const int* in_sizes, int n_in,
                              void* d_out, int out_size)
{
    const float* Y = (const float*)d_in[0];   // output_before (2048, 256)
    const float* Z = (const float*)d_in[1];   // z_mlr (128, 256)
    const float* R = (const float*)d_in[2];   // mlr_r (128, 1)
    float* Out = (float*)d_out;               // (2048, 128)

    size_t shmem = (size_t)(BM * RPITCH + BN * RPITCH + NTHREADS + 64 +
                            5 * BN + BM) * sizeof(float);
    cudaFuncSetAttribute(mlr_logits_kernel,
                         cudaFuncAttributeMaxDynamicSharedMemorySize, (int)shmem);

    dim3 grid(BB / BM, KK / BN);   // 64 x 8 = 512 blocks
    dim3 block(NTHREADS);
    mlr_logits_kernel<<<grid, block, shmem>>>(Y, Z, R, Out);
}

// round 8
// speedup vs baseline: 1.9851x; 1.9851x over previous
#include <cuda_runtime.h>
#include <cuda_bf16.h>
#include <math.h>
#include <stdint.h>

// Problem constants (fixed by setup_inputs): B=2048, K=128, D=256
#define BB 2048
#define KK 128
#define DD 256

#define BM 64       // b-rows per block
#define BN 32       // k-cols per block
#define PB 264      // row pitch in bf16 units (528 bytes; 16B-aligned, conflict-free ldmatrix)
#define NTHREADS 256

__device__ __forceinline__ uint32_t cvta_smem(const void* p) {
    return (uint32_t)__cvta_generic_to_shared(p);
}

__device__ __forceinline__ void ldmat_x4(uint32_t* r, uint32_t addr) {
    asm volatile("ldmatrix.sync.aligned.m8n8.x4.shared.b16 {%0,%1,%2,%3}, [%4];"
                 : "=r"(r[0]), "=r"(r[1]), "=r"(r[2]), "=r"(r[3]) : "r"(addr));
}

__device__ __forceinline__ void mma_bf16(float* d, const uint32_t* a, uint32_t b0, uint32_t b1) {
    asm volatile("mma.sync.aligned.m16n8k16.row.col.f32.bf16.bf16.f32 "
                 "{%0,%1,%2,%3}, {%4,%5,%6,%7}, {%8,%9}, {%0,%1,%2,%3};"
                 : "+f"(d[0]), "+f"(d[1]), "+f"(d[2]), "+f"(d[3])
                 : "r"(a[0]), "r"(a[1]), "r"(a[2]), "r"(a[3]), "r"(b0), "r"(b1));
}

__device__ __forceinline__ uint32_t bits2(__nv_bfloat162 v) {
    return *reinterpret_cast<uint32_t*>(&v);
}

// logits[b][k] = 2*an_k * asinh( 2*(S*xa + T*ya)*den / (den^2 - (S^2*x2 + 2*S*T*xy + T^2*y2)) )
// g = z_k . y_b, xy = s_k*g, ya = t_k*g, S = 1+2xy+y2, den = 1+2xy+x2*y2, T = 1-x2

__global__ void __launch_bounds__(NTHREADS, 1)
mlr_logits_kernel(const float* __restrict__ Y,   // output_before (B, D)
                  const float* __restrict__ Z,   // z_mlr (K, D)
                  const float* __restrict__ R,   // mlr_r (K, 1)
                  float* __restrict__ Out)       // (B, K)
{
    extern __shared__ char smem[];
    __nv_bfloat16* AHI = reinterpret_cast<__nv_bfloat16*>(smem);           // BM*PB
    __nv_bfloat16* ALO = AHI + BM * PB;                                     // BM*PB
    __nv_bfloat16* ZHI = ALO + BM * PB;                                     // BN*PB
    __nv_bfloat16* ZLO = ZHI + BN * PB;                                     // BN*PB
    float* part  = reinterpret_cast<float*>(ZLO + BN * PB);                 // 256
    float* zprt  = part + NTHREADS;                                         // 128
    float* s_s   = zprt + 128;                                              // BN
    float* s_t   = s_s + BN;
    float* s_x2  = s_t + BN;
    float* s_xa  = s_x2 + BN;
    float* s_an2 = s_xa + BN;
    float* s_y2  = s_an2 + BN;                                              // BM

    const int tid  = threadIdx.x;
    const int b0   = blockIdx.x * BM;
    const int k0   = blockIdx.y * BN;
    const int warp = tid >> 5;
    const int lane = tid & 31;

    // ---- load + bf16-split Y tile (BM x D): hi/lo plain rows ----
    #pragma unroll
    for (int idx = tid; idx < BM * (DD / 4); idx += NTHREADS) {
        int row = idx >> 6;
        int c4  = idx & 63;
        float4 v = reinterpret_cast<const float4*>(Y + (size_t)(b0 + row) * DD)[c4];
        __nv_bfloat162 h01 = __float22bfloat162_rn(make_float2(v.x, v.y));
        __nv_bfloat162 h23 = __float22bfloat162_rn(make_float2(v.z, v.w));
        float2 hf01 = __bfloat1622float2(h01);
        float2 hf23 = __bfloat1622float2(h23);
        __nv_bfloat162 l01 = __float22bfloat162_rn(make_float2(v.x - hf01.x, v.y - hf01.y));
        __nv_bfloat162 l23 = __float22bfloat162_rn(make_float2(v.z - hf23.x, v.w - hf23.y));
        uint2 hu = make_uint2(bits2(h01), bits2(h23));
        uint2 lu = make_uint2(bits2(l01), bits2(l23));
        *reinterpret_cast<uint2*>(&AHI[row * PB + c4 * 4]) = hu;
        *reinterpret_cast<uint2*>(&ALO[row * PB + c4 * 4]) = lu;
    }
    // ---- load + split Z tile (BN x D) ----
    #pragma unroll
    for (int idx = tid; idx < BN * (DD / 4); idx += NTHREADS) {
        int row = idx >> 6;
        int c4  = idx & 63;
        float4 v = reinterpret_cast<const float4*>(Z + (size_t)(k0 + row) * DD)[c4];
        __nv_bfloat162 h01 = __float22bfloat162_rn(make_float2(v.x, v.y));
        __nv_bfloat162 h23 = __float22bfloat162_rn(make_float2(v.z, v.w));
        float2 hf01 = __bfloat1622float2(h01);
        float2 hf23 = __bfloat1622float2(h23);
        __nv_bfloat162 l01 = __float22bfloat162_rn(make_float2(v.x - hf01.x, v.y - hf01.y));
        __nv_bfloat162 l23 = __float22bfloat162_rn(make_float2(v.z - hf23.x, v.w - hf23.y));
        uint2 hu = make_uint2(bits2(h01), bits2(h23));
        uint2 lu = make_uint2(bits2(l01), bits2(l23));
        *reinterpret_cast<uint2*>(&ZHI[row * PB + c4 * 4]) = hu;
        *reinterpret_cast<uint2*>(&ZLO[row * PB + c4 * 4]) = lu;
    }
    __syncthreads();

    // ---- Y row norms: 4 threads per row (v = hi + lo) ----
    {
        const int row = tid >> 2;    // 0..63
        const int q   = tid & 3;
        const uint4* ph = reinterpret_cast<const uint4*>(&AHI[row * PB + q * 64]);
        const uint4* pl = reinterpret_cast<const uint4*>(&ALO[row * PB + q * 64]);
        float acc = 0.f;
        #pragma unroll
        for (int j = 0; j < 8; j++) {
            uint4 h = ph[j], l = pl[j];
            const uint32_t hw[4] = {h.x, h.y, h.z, h.w};
            const uint32_t lw[4] = {l.x, l.y, l.z, l.w};
            #pragma unroll
            for (int m = 0; m < 4; m++) {
                float2 hf = __bfloat1622float2(*reinterpret_cast<const __nv_bfloat162*>(&hw[m]));
                float2 lf = __bfloat1622float2(*reinterpret_cast<const __nv_bfloat162*>(&lw[m]));
                float v0 = hf.x + lf.x, v1 = hf.y + lf.y;
                acc = fmaf(v0, v0, acc);
                acc = fmaf(v1, v1, acc);
            }
        }
        part[tid] = acc;
    }
    // ---- Z row norms: threads 0..127, 4 per row ----
    if (tid < 4 * BN) {
        const int row = tid >> 2;    // 0..31
        const int q   = tid & 3;
        const uint4* ph = reinterpret_cast<const uint4*>(&ZHI[row * PB + q * 64]);
        const uint4* pl = reinterpret_cast<const uint4*>(&ZLO[row * PB + q * 64]);
        float acc = 0.f;
        #pragma unroll
        for (int j = 0; j < 8; j++) {
            uint4 h = ph[j], l = pl[j];
            const uint32_t hw[4] = {h.x, h.y, h.z, h.w};
            const uint32_t lw[4] = {l.x, l.y, l.z, l.w};
            #pragma unroll
            for (int m = 0; m < 4; m++) {
                float2 hf = __bfloat1622float2(*reinterpret_cast<const __nv_bfloat162*>(&hw[m]));
                float2 lf = __bfloat1622float2(*reinterpret_cast<const __nv_bfloat162*>(&lw[m]));
                float v0 = hf.x + lf.x, v1 = hf.y + lf.y;
                acc = fmaf(v0, v0, acc);
                acc = fmaf(v1, v1, acc);
            }
        }
        zprt[tid] = acc;
    }
    __syncthreads();

    if (tid < BM) {
        s_y2[tid] = (part[tid * 4 + 0] + part[tid * 4 + 1]) +
                    (part[tid * 4 + 2] + part[tid * 4 + 3]);
    } else if (tid < BM + BN) {
        int row = tid - BM;
        float zn2 = (zprt[row * 4 + 0] + zprt[row * 4 + 1]) +
                    (zprt[row * 4 + 2] + zprt[row * 4 + 3]);
        float zn  = sqrtf(zn2);
        float r   = R[k0 + row];
        float un  = fmaxf(fabsf(r) * zn, 1e-15f);
        float s   = -tanhf(un) * r / un;
        float th  = tanhf(r);
        float ic2 = 1.0f - th * th;      // 1/cosh(r)^2
        float an  = zn * ic2;
        float t   = ic2 / fmaxf(an, 1e-12f);
        s_s[row]   = s;
        s_t[row]   = t;
        s_x2[row]  = s * s * zn2;
        s_xa[row]  = s * zn2 * t;
        s_an2[row] = 2.0f * an;
    }
    __syncthreads();

    // ---- tensor GEMM: 8 warps (4m x 2n), warp tile 16m x 16n, m16n8k16 bf16 ----
    const int mw = (warp >> 1) * 16;      // 0,16,32,48
    const int nw = (warp & 1) * 16;       // 0,16
    const int g  = lane >> 2;
    const int c  = lane & 3;

    // ldmatrix lane->address mapping
    const int rowA  = mw + (lane & 15);
    const int offA  = (lane >> 4) * 16;            // bytes: k 0-7 / k 8-15 halves
    const int rowB  = nw + ((lane >> 4) * 8) + (lane & 7);
    const int offB  = (lane & 8) * 2;              // 0 or 16 bytes

    uint32_t aAH = cvta_smem(AHI) + rowA * (PB * 2) + offA;
    uint32_t aAL = cvta_smem(ALO) + rowA * (PB * 2) + offA;
    uint32_t aBH = cvta_smem(ZHI) + rowB * (PB * 2) + offB;
    uint32_t aBL = cvta_smem(ZLO) + rowB * (PB * 2) + offB;

    float accP[2][4] = {{0,0,0,0},{0,0,0,0}};   // hi*hi
    float accQ[2][4] = {{0,0,0,0},{0,0,0,0}};   // hi*lo
    float accS[2][4] = {{0,0,0,0},{0,0,0,0}};   // lo*hi

    uint32_t aH[2][4], aL[2][4], bH[2][4], bL[2][4];

    ldmat_x4(aH[0], aAH);
    ldmat_x4(aL[0], aAL);
    ldmat_x4(bH[0], aBH);
    ldmat_x4(bL[0], aBL);

    #pragma unroll
    for (int t = 0; t < DD / 16; t++) {
        const int cur = t & 1, nxt = cur ^ 1;
        if (t < DD / 16 - 1) {
            const uint32_t o = (t + 1) * 32;   // 16 bf16 = 32 bytes per k-step
            ldmat_x4(aH[nxt], aAH + o);
            ldmat_x4(aL[nxt], aAL + o);
            ldmat_x4(bH[nxt], aBH + o);
            ldmat_x4(bL[nxt], aBL + o);
        }
        // n-tile 0 uses b regs {0,1}, n-tile 1 uses {2,3}
        mma_bf16(accP[0], aH[cur], bH[cur][0], bH[cur][1]);
        mma_bf16(accP[1], aH[cur], bH[cur][2], bH[cur][3]);
        mma_bf16(accQ[0], aH[cur], bL[cur][0], bL[cur][1]);
        mma_bf16(accQ[1], aH[cur], bL[cur][2], bL[cur][3]);
        mma_bf16(accS[0], aL[cur], bH[cur][0], bH[cur][1]);
        mma_bf16(accS[1], aL[cur], bH[cur][2], bH[cur][3]);
    }

    // ---- epilogue: 8 outputs per thread, float2 stores ----
    const int brow[2] = { mw + g, mw + g + 8 };

    #pragma unroll
    for (int nt = 0; nt < 2; nt++) {
        const int kl = nw + nt * 8 + 2 * c;       // block-local k col (even)
        const float s0  = s_s[kl],   s1  = s_s[kl + 1];
        const float t0  = s_t[kl],   t1  = s_t[kl + 1];
        const float x20 = s_x2[kl],  x21 = s_x2[kl + 1];
        const float xa0 = s_xa[kl],  xa1 = s_xa[kl + 1];
        const float a20 = s_an2[kl], a21 = s_an2[kl + 1];
        const float T0 = 1.0f - x20, T1 = 1.0f - x21;
        #pragma unroll
        for (int i = 0; i < 2; i++) {
            const float y2 = s_y2[brow[i]];
            const float g0 = accP[nt][i * 2 + 0] + accQ[nt][i * 2 + 0] + accS[nt][i * 2 + 0];
            const float g1 = accP[nt][i * 2 + 1] + accQ[nt][i * 2 + 1] + accS[nt][i * 2 + 1];

            float xy = s0 * g0;
            float ya = t0 * g0;
            float Sv  = fmaf(2.0f, xy, 1.0f) + y2;
            float den = fmaf(2.0f, xy, 1.0f) + x20 * y2;
            float Pv  = Sv * Sv * x20 + 2.0f * Sv * T0 * xy + T0 * T0 * y2;
            float v0  = 2.0f * (Sv * xa0 + T0 * ya) * den / (den * den - Pv);
            float o0  = a20 * asinhf(v0);

            xy  = s1 * g1;
            ya  = t1 * g1;
            Sv  = fmaf(2.0f, xy, 1.0f) + y2;
            den = fmaf(2.0f, xy, 1.0f) + x21 * y2;
            Pv  = Sv * Sv * x21 + 2.0f * Sv * T1 * xy + T1 * T1 * y2;
            float v1 = 2.0f * (Sv * xa1 + T1 * ya) * den / (den * den - Pv);
            float o1 = a21 * asinhf(v1);

            *reinterpret_cast<float2*>(&Out[(size_t)(b0 + brow[i]) * KK + (k0 + kl)]) =
                make_float2(o0, o1);
        }
    }
}

extern "C" void kernel_launch(void* const* d_in, const int* in_sizes, int n_in,
                              void* d_out, int out_size)
{
    const float* Y = (const float*)d_in[0];   // output_before (2048, 256)
    const float* Z = (const float*)d_in[1];   // z_mlr (128, 256)
    const float* R = (const float*)d_in[2];   // mlr_r (128, 1)
    float* Out = (float*)d_out;               // (2048, 128)

    size_t shmem = (size_t)(2 * BM * PB + 2 * BN * PB) * sizeof(__nv_bfloat16)
                 + (size_t)(NTHREADS + 128 + 5 * BN + BM) * sizeof(float);
    cudaFuncSetAttribute(mlr_logits_kernel,
                         cudaFuncAttributeMaxDynamicSharedMemorySize, (int)shmem);

    dim3 grid(BB / BM, KK / BN);   // 32 x 4 = 128 blocks (single wave)
    dim3 block(NTHREADS);
    mlr_logits_kernel<<<grid, block, shmem>>>(Y, Z, R, Out);
}